// round 7
// baseline (speedup 1.0000x reference)
#include <cuda_runtime.h>
#include <cuda_fp16.h>
#include <cstdint>
#include <cstddef>

#define NROWS 200000
#define DIMX 256
#define HID 128
#define NSEG 512

constexpr int TILE_M = 128;
constexpr int NTILES = (NROWS + TILE_M - 1) / TILE_M;  // 1563
constexpr int TPB = 256;  // 8 warps: 4 m-groups x 2 n-groups

#define NCHEB 16
#define NNODE 32
#define CLAMP 4.5f
#define RANGE_T (CLAMP * CLAMP)

// ---- smem layout (bytes) ----
constexpr int SM_B1 = 0;           // float[128]
constexpr int SM_W2 = 512;         // float[128]
constexpr int SM_COEF = 1024;      // float[16]
constexpr int SM_SPART = 1152;     // float[128][2]
constexpr int SM_WHI = 4096;       // 4 panels x 16KB (SW128, fp16)
constexpr int SM_WLO = SM_WHI + 65536;
constexpr int SMEM_TOTAL = SM_WLO + 65536;  // 135168

__device__ float g_scores[NROWS];
__device__ int g_seg[NSEG + 1];
__device__ __half g_wt_hi[HID * DIMX];  // [n][k]
__device__ __half g_wt_lo[HID * DIMX];
__device__ float g_coef[NCHEB];

// ---------------- helpers ----------------
__device__ __forceinline__ uint32_t smem_u32(const void *p) {
    uint32_t a;
    asm("{ .reg .u64 t; cvta.to.shared.u64 t, %1; cvt.u32.u64 %0, t; }" : "=r"(a) : "l"(p));
    return a;
}
#define SWZ(off) ((uint32_t)(off) ^ ((((uint32_t)(off)) >> 3) & 0x70u))

// pack two fp32 -> f16x2 (hi arg -> upper half, matching bf16x2 convention verified earlier)
__device__ __forceinline__ uint32_t packh(float lo, float hi) {
    uint32_t r;
    asm("cvt.rn.f16x2.f32 %0, %1, %2;" : "=r"(r) : "f"(hi), "f"(lo));
    return r;
}

__device__ __forceinline__ void ldsm4(uint32_t *r, uint32_t addr) {
    asm volatile("ldmatrix.sync.aligned.m8n8.x4.shared.b16 {%0,%1,%2,%3}, [%4];"
                 : "=r"(r[0]), "=r"(r[1]), "=r"(r[2]), "=r"(r[3]) : "r"(addr));
}
__device__ __forceinline__ void mma16816(float *d, const uint32_t *a, const uint32_t *b) {
    asm volatile("mma.sync.aligned.m16n8k16.row.col.f32.f16.f16.f32 "
                 "{%0,%1,%2,%3}, {%4,%5,%6,%7}, {%8,%9}, {%0,%1,%2,%3};"
                 : "+f"(d[0]), "+f"(d[1]), "+f"(d[2]), "+f"(d[3])
                 : "r"(a[0]), "r"(a[1]), "r"(a[2]), "r"(a[3]), "r"(b[0]), "r"(b[1]));
}

// ---------------- prep: W1 -> Wt fp16 hi/lo ----------------
__global__ void prep_w(const float *__restrict__ W1) {
    int i = blockIdx.x * 256 + threadIdx.x;  // 32768
    int k = i >> 7, n = i & 127;             // W1[k][n]
    float v = W1[i];
    __half h = __float2half_rn(v);
    g_wt_hi[n * DIMX + k] = h;
    g_wt_lo[n * DIMX + k] = __float2half_rn(v - __half2float(h));
}

// ---------------- prep: Chebyshev->monomial coeffs of tanh(sqrt(t))/sqrt(t) ----------------
__global__ void prep_cheb() {
    __shared__ double cheb[NCHEB], mono[NCHEB];
    int t = threadIdx.x;  // 64 threads
    if (t < NCHEB) { cheb[t] = 0.0; mono[t] = 0.0; }
    __syncthreads();
    if (t < NNODE) {
        double th = 3.14159265358979323846 * (t + 0.5) / NNODE;
        double c1 = cos(th);
        double tt = (double)RANGE_T * 0.5 * (c1 + 1.0);
        double xx = sqrt(tt);
        double g = (xx < 1e-8) ? 1.0 : (tanh(xx) / xx);
        double w = 2.0 / NNODE;
        double Tm = 1.0, Tc = c1;
        atomicAdd(&cheb[0], g * w);
        for (int k = 1; k < NCHEB; k++) {
            atomicAdd(&cheb[k], g * Tc * w);
            double Tn = 2.0 * c1 * Tc - Tm;
            Tm = Tc; Tc = Tn;
        }
    }
    __syncthreads();
    if (t < NCHEB) {
        double ck = cheb[t] * ((t == 0) ? 0.5 : 1.0);
        if (t == 0) {
            atomicAdd(&mono[0], ck);
        } else {
            double fact[NCHEB];
            fact[0] = 1.0;
            for (int i = 1; i < NCHEB; i++) fact[i] = fact[i - 1] * i;
            for (int m = 0; 2 * m <= t; m++) {
                int p = t - 2 * m;
                double p2 = (p >= 1) ? (double)(1ull << (p - 1)) : 0.5;
                double cf = (double)t * fact[t - m - 1] / (fact[m] * fact[p]) * p2;
                if (m & 1) cf = -cf;
                atomicAdd(&mono[p], ck * cf);
            }
        }
    }
    __syncthreads();
    if (t < NCHEB) g_coef[t] = (float)mono[t];
}

__device__ __forceinline__ float ftanh(float x, const float *cf) {
    float xc = fminf(fmaxf(x, -CLAMP), CLAMP);
    float s = fmaf(xc * xc, 2.0f / RANGE_T, -1.0f);
    float p = cf[NCHEB - 1];
    #pragma unroll
    for (int i = NCHEB - 2; i >= 0; i--) p = fmaf(p, s, cf[i]);
    return xc * p;
}

// ---------------- scores: fp16 2-term, A direct-from-global, sync-free mainloop ----------------
__global__ void __launch_bounds__(TPB, 1)
scores_kernel(const float *__restrict__ x, const float *__restrict__ b1,
              const float *__restrict__ W2) {
    extern __shared__ char smem[];
    const uint32_t sb = smem_u32(smem);
    const int tid = threadIdx.x;
    const int wid = tid >> 5, lane = tid & 31;
    const int mg = wid >> 1, ng = wid & 1;  // rows 32*mg.., cols 64*ng..

    if (tid < HID) {
        ((float *)(smem + SM_B1))[tid] = b1[tid];
        ((float *)(smem + SM_W2))[tid] = W2[tid];
    }
    if (tid < NCHEB) ((float *)(smem + SM_COEF))[tid] = g_coef[tid];
    // stage Wt hi/lo into SW128 panels (panel c: k in [64c, 64c+64))
    for (int i = tid; i < HID * (DIMX / 4); i += TPB) {
        int n = i >> 6, k4 = i & 63;
        uint2 vh = *(const uint2 *)(g_wt_hi + n * DIMX + k4 * 4);
        uint2 vl = *(const uint2 *)(g_wt_lo + n * DIMX + k4 * 4);
        uint32_t off = SWZ(n * 128 + (k4 & 15) * 8) + (uint32_t)(k4 >> 4) * 16384u;
        *(uint2 *)(smem + SM_WHI + off) = vh;
        *(uint2 *)(smem + SM_WLO + off) = vl;
    }
    __syncthreads();

    float *spart = (float *)(smem + SM_SPART);
    const float *b1s = (const float *)(smem + SM_B1);
    const float *w2s = (const float *)(smem + SM_W2);

    const int lr = lane >> 2, cq = lane & 3;
    const int bn = ng * 64 + ((lane >> 4) & 1) * 8 + (lane & 7);
    const int bkb = ((lane >> 3) & 1) * 8;

    for (int tile = blockIdx.x; tile < NTILES; tile += gridDim.x) {
        const size_t r0 = (size_t)tile * TILE_M;
        const size_t rb = r0 + mg * 32 + lr;
        // clamp pad rows into valid memory; their acc rows are garbage but never stored
        const float2 *p0 = (const float2 *)x + min(rb, (size_t)(NROWS - 1)) * 128;
        const float2 *p1 = (const float2 *)x + min(rb + 8, (size_t)(NROWS - 1)) * 128;
        const float2 *p2 = (const float2 *)x + min(rb + 16, (size_t)(NROWS - 1)) * 128;
        const float2 *p3 = (const float2 *)x + min(rb + 24, (size_t)(NROWS - 1)) * 128;

        // acc init = b1 (bias folded)
        float acc[2][8][4];
        #pragma unroll
        for (int mt = 0; mt < 2; mt++)
            #pragma unroll
            for (int nt = 0; nt < 8; nt++) {
                int c0 = ng * 64 + nt * 8 + cq * 2;
                acc[mt][nt][0] = b1s[c0];
                acc[mt][nt][1] = b1s[c0 + 1];
                acc[mt][nt][2] = acc[mt][nt][0];
                acc[mt][nt][3] = acc[mt][nt][1];
            }

        float2 buf[2][8];
        {
            const int o = cq;
            buf[0][0] = p0[o]; buf[0][1] = p1[o]; buf[0][2] = p0[o + 4]; buf[0][3] = p1[o + 4];
            buf[0][4] = p2[o]; buf[0][5] = p3[o]; buf[0][6] = p2[o + 4]; buf[0][7] = p3[o + 4];
        }

        #pragma unroll 2
        for (int ks = 0; ks < 16; ks++) {
            const int cb = ks & 1;
            if (ks < 15) {
                const int o = (ks + 1) * 8 + cq;
                float2 *nb = buf[cb ^ 1];
                nb[0] = p0[o]; nb[1] = p1[o]; nb[2] = p0[o + 4]; nb[3] = p1[o + 4];
                nb[4] = p2[o]; nb[5] = p3[o]; nb[6] = p2[o + 4]; nb[7] = p3[o + 4];
            }
            // convert A frags: single fp16 (8 cvt)
            uint32_t ah[2][4];
            #pragma unroll
            for (int mt = 0; mt < 2; mt++)
                #pragma unroll
                for (int j = 0; j < 4; j++) {
                    float2 v = buf[cb][mt * 4 + j];
                    ah[mt][j] = packh(v.x, v.y);
                }
            // ldsm B frags (hi + lo panels)
            uint32_t bh[4][4], bl[4][4];
            const uint32_t whp = sb + SM_WHI + (uint32_t)(ks >> 2) * 16384u;
            const uint32_t wlp = sb + SM_WLO + (uint32_t)(ks >> 2) * 16384u;
            const int ki = (ks & 3) * 16 + bkb;
            #pragma unroll
            for (int nt2 = 0; nt2 < 4; nt2++) {
                uint32_t off = SWZ((bn + nt2 * 16) * 128 + ki * 2);
                ldsm4(bh[nt2], whp + off);
                ldsm4(bl[nt2], wlp + off);
            }
            // 32 HMMA: ah*(wh) + ah*(wl)
            #pragma unroll
            for (int mt = 0; mt < 2; mt++)
                #pragma unroll
                for (int nt = 0; nt < 8; nt++) {
                    const uint32_t *bhp = &bh[nt >> 1][(nt & 1) * 2];
                    const uint32_t *blp = &bl[nt >> 1][(nt & 1) * 2];
                    mma16816(acc[mt][nt], ah[mt], bhp);
                    mma16816(acc[mt][nt], ah[mt], blp);
                }
        }

        // ---- epilogue: tanh poly + dot W2 ----
        {
            float cf[NCHEB];
            #pragma unroll
            for (int i = 0; i < NCHEB; i++) cf[i] = ((const float *)(smem + SM_COEF))[i];
            #pragma unroll
            for (int mt = 0; mt < 2; mt++)
                #pragma unroll
                for (int qh = 0; qh < 2; qh++) {
                    float p = 0.f;
                    #pragma unroll
                    for (int nt = 0; nt < 8; nt++) {
                        int c0 = ng * 64 + nt * 8 + cq * 2;
                        p += ftanh(acc[mt][nt][qh * 2 + 0], cf) * w2s[c0] +
                             ftanh(acc[mt][nt][qh * 2 + 1], cf) * w2s[c0 + 1];
                    }
                    p += __shfl_xor_sync(0xffffffffu, p, 1);
                    p += __shfl_xor_sync(0xffffffffu, p, 2);
                    if (cq == 0)
                        spart[(mg * 32 + mt * 16 + qh * 8 + lr) * 2 + ng] = p;
                }
        }
        __syncthreads();
        if (tid < 128) {
            size_t row = r0 + tid;
            if (row < NROWS) g_scores[row] = spart[tid * 2] + spart[tid * 2 + 1];
        }
        __syncthreads();
    }
}

// ---------------- weights: one warp per segment, no block barriers ----------------
__device__ __forceinline__ int lbound(const int *__restrict__ b, int target) {
    int lo = 0, hi = NROWS;
    while (lo < hi) {
        int mid = (lo + hi) >> 1;
        if (b[mid] < target) lo = mid + 1;
        else hi = mid;
    }
    return lo;
}

__global__ void __launch_bounds__(128)
weights_kernel(const int *__restrict__ batch, float *__restrict__ out) {
    const int w = blockIdx.x * 4 + (threadIdx.x >> 5);  // segment id, 512 warps
    const int lane = threadIdx.x & 31;
    if (w >= NSEG) return;

    int s = lbound(batch, w);          // each lane computes (identical) — cheap, cached
    int e = lbound(batch, w + 1);
    if (lane == 0) {
        g_seg[w] = s;
        if (w == NSEG - 1) g_seg[NSEG] = NROWS;
    }
    // zero out row
    float4 *orow = (float4 *)(out + (size_t)w * DIMX);
    #pragma unroll
    for (int i = lane; i < 64; i += 32) orow[i] = make_float4(0.f, 0.f, 0.f, 0.f);

    float m = -3.4e38f;
    for (int i = s + lane; i < e; i += 32) m = fmaxf(m, g_scores[i]);
    #pragma unroll
    for (int off = 16; off; off >>= 1) m = fmaxf(m, __shfl_xor_sync(0xffffffffu, m, off));

    float ss = 0.f;
    for (int i = s + lane; i < e; i += 32) ss += expf(g_scores[i] - m);
    #pragma unroll
    for (int off = 16; off; off >>= 1) ss += __shfl_xor_sync(0xffffffffu, ss, off);

    const float inv = 1.0f / ss;
    for (int i = s + lane; i < e; i += 32) g_scores[i] = expf(g_scores[i] - m) * inv;
}

// ---------------- pool2: uniform row blocks + per-segment atomic flush ----------------
constexpr int RPB = 256;
constexpr int PBLK = (NROWS + RPB - 1) / RPB;  // 782

__global__ void __launch_bounds__(256)
pool2_kernel(const float *__restrict__ x, const int *__restrict__ batch,
             float *__restrict__ out) {
    const int tid = threadIdx.x;
    const int r0 = blockIdx.x * RPB;
    const int rend = min(r0 + RPB, NROWS);
    const int g0 = batch[r0], g1 = batch[rend - 1];

    for (int g = g0; g <= g1; g++) {
        const int s = max(g_seg[g], r0);
        const int e = min(g_seg[g + 1], rend);
        if (s >= e) continue;
        float a0 = 0.f, a1 = 0.f, a2 = 0.f, a3 = 0.f;
        float a4 = 0.f, a5 = 0.f, a6 = 0.f, a7 = 0.f;
        int r = s;
        for (; r + 8 <= e; r += 8) {
            a0 = fmaf(g_scores[r + 0], x[(size_t)(r + 0) * DIMX + tid], a0);
            a1 = fmaf(g_scores[r + 1], x[(size_t)(r + 1) * DIMX + tid], a1);
            a2 = fmaf(g_scores[r + 2], x[(size_t)(r + 2) * DIMX + tid], a2);
            a3 = fmaf(g_scores[r + 3], x[(size_t)(r + 3) * DIMX + tid], a3);
            a4 = fmaf(g_scores[r + 4], x[(size_t)(r + 4) * DIMX + tid], a4);
            a5 = fmaf(g_scores[r + 5], x[(size_t)(r + 5) * DIMX + tid], a5);
            a6 = fmaf(g_scores[r + 6], x[(size_t)(r + 6) * DIMX + tid], a6);
            a7 = fmaf(g_scores[r + 7], x[(size_t)(r + 7) * DIMX + tid], a7);
        }
        for (; r < e; r++) a0 = fmaf(g_scores[r], x[(size_t)r * DIMX + tid], a0);
        atomicAdd(&out[(size_t)g * DIMX + tid],
                  ((a0 + a1) + (a2 + a3)) + ((a4 + a5) + (a6 + a7)));
    }
}

// ---------------- launch ----------------
extern "C" void kernel_launch(void *const *d_in, const int *in_sizes, int n_in,
                              void *d_out, int out_size) {
    (void)in_sizes; (void)n_in; (void)out_size;
    const float *x = (const float *)d_in[0];
    const int *batch = (const int *)d_in[1];
    const float *W1 = (const float *)d_in[2];
    const float *b1 = (const float *)d_in[3];
    const float *W2 = (const float *)d_in[4];
    float *out = (float *)d_out;

    static int grid_s = 0;
    if (grid_s == 0) {
        int sm = 148;
        cudaDeviceGetAttribute(&sm, cudaDevAttrMultiProcessorCount, 0);
        grid_s = sm;
        cudaFuncSetAttribute(scores_kernel, cudaFuncAttributeMaxDynamicSharedMemorySize,
                             SMEM_TOTAL);
    }
    prep_w<<<HID * DIMX / 256, 256>>>(W1);
    prep_cheb<<<1, 64>>>();
    scores_kernel<<<grid_s, TPB, SMEM_TOTAL>>>(x, b1, W2);
    weights_kernel<<<(NSEG + 3) / 4, 128>>>(batch, out);
    pool2_kernel<<<PBLK, 256>>>(x, batch, out);
}